// round 10
// baseline (speedup 1.0000x reference)
#include <cuda_runtime.h>
#include <cuda_bf16.h>
#include <cuda_pipeline.h>
#include <cstdint>

// OverlapPatchEmbed: x (B=64, C=3, H=224, W=224) f32 -> out (B, 729, C, 256) f32
// out[b][pi*27+pj][c][r*16+s] = x[b][c][pi*8+r][pj*8+s]
//
// Triple-band (block = (b, c, g), pi = 3g..3g+2) with STAGED cp.async drain:
// three commit groups (rows 0-15 / 16-23 / 24-31) issued up front; band 0's
// store starts after only group 0 lands (wait_prior(2)), overlapping the
// remaining load traffic with store work. Pitch-60 smem: conflict-free
// LDS.128; stores are coalesced streaming STG.128 (__stcs).

namespace {
constexpr int B  = 64;
constexpr int C  = 3;
constexpr int H  = 224;
constexpr int W  = 224;      // 56 float4 per row
constexpr int N  = 27;
constexpr int G  = 9;        // pi groups of 3
constexpr int TPB = 256;

constexpr int W4      = W / 4;          // 56
constexpr int PITCH4  = 60;             // 240-float pitch (mod 32 == 16): conflict-free
constexpr int STORE_V = N * 64;         // 1728 float4 per band
constexpr int NBLOCKS = B * C * G;      // 1728
constexpr int SK = 7;                   // ceil(1728/256)

// load stage extents (rows), each a multiple-of-... issued round-robin by all threads
constexpr int S0_V = 16 * W4;           // rows 0-15  : 896 float4
constexpr int S1_V = 8  * W4;           // rows 16-23 : 448
constexpr int S2_V = 8  * W4;           // rows 24-31 : 448
}

__global__ __launch_bounds__(TPB, 7)
void overlap_patch_kernel(const float4* __restrict__ x, float4* __restrict__ out)
{
    __shared__ float4 s[32 * PITCH4];   // 30720 bytes

    const int bx  = blockIdx.x;
    const int g   = bx % G;
    const int c   = (bx / G) % C;
    const int b   = bx / (G * C);
    const int tid = threadIdx.x;
    const int pi0 = g * 3;

    const int in_base = ((b * C + c) * H + pi0 * 8) * W4;   // float4 index

    // ---- issue all three load stages up front, one commit group each ----
    // stage 0: rows 0-15
    #pragma unroll
    for (int k = 0; k < 4; k++) {                 // 896 = 3.5*256 -> 4 iters
        int i = tid + k * TPB;
        if (i < S0_V) {
            int row = i / W4, col = i - row * W4;
            __pipeline_memcpy_async(&s[row * PITCH4 + col], &x[in_base + i], 16);
        }
    }
    __pipeline_commit();
    // stage 1: rows 16-23
    #pragma unroll
    for (int k = 0; k < 2; k++) {                 // 448 -> 2 iters
        int i = tid + k * TPB;
        if (i < S1_V) {
            int row = 16 + i / W4, col = i - (i / W4) * W4;
            __pipeline_memcpy_async(&s[row * PITCH4 + col],
                                    &x[in_base + 16 * W4 + i], 16);
        }
    }
    __pipeline_commit();
    // stage 2: rows 24-31
    #pragma unroll
    for (int k = 0; k < 2; k++) {
        int i = tid + k * TPB;
        if (i < S2_V) {
            int row = 24 + i / W4, col = i - (i / W4) * W4;
            __pipeline_memcpy_async(&s[row * PITCH4 + col],
                                    &x[in_base + 24 * W4 + i], 16);
        }
    }
    __pipeline_commit();

    // ---- staged drain + store: band sub needs rows 8*sub .. 8*sub+15 ----
    #pragma unroll
    for (int sub = 0; sub < 3; sub++) {
        if (sub == 0)      __pipeline_wait_prior(2);
        else if (sub == 1) __pipeline_wait_prior(1);
        else               __pipeline_wait_prior(0);
        __syncthreads();   // all warps' contributions to this stage visible

        const int pi  = pi0 + sub;
        const int ob0 = ((b * (N * N) + pi * N) * C + c) * 64;
        const int srow0 = sub * 8;

        float4 sv[SK];
        #pragma unroll
        for (int k = 0; k < SK; k++) {
            int j = tid + k * TPB;
            if (j < STORE_V) {
                int pj = j >> 6;
                int q  = j & 63;
                int r  = q >> 2;
                int s4 = q & 3;
                sv[k] = s[(srow0 + r) * PITCH4 + pj * 2 + s4];
            }
        }
        #pragma unroll
        for (int k = 0; k < SK; k++) {
            int j = tid + k * TPB;
            if (j < STORE_V) {
                int pj = j >> 6;
                int q  = j & 63;
                __stcs(&out[ob0 + pj * (C * 64) + q], sv[k]);
            }
        }
    }
}

extern "C" void kernel_launch(void* const* d_in, const int* in_sizes, int n_in,
                              void* d_out, int out_size)
{
    const float4* x = (const float4*)d_in[0];
    float4* out = (float4*)d_out;
    overlap_patch_kernel<<<NBLOCKS, TPB>>>(x, out);
}

// round 11
// speedup vs baseline: 1.2821x; 1.2821x over previous
#include <cuda_runtime.h>
#include <cuda_bf16.h>
#include <cuda_pipeline.h>
#include <cstdint>

// OverlapPatchEmbed: x (B=64, C=3, H=224, W=224) f32 -> out (B, 729, C, 256) f32
// out[b][pi*27+pj][c][r*16+s] = x[b][c][pi*8+r][pj*8+s]
//
// Triple-band (pi = 3g..3g+2 per block), smem-staged, cp.async loads,
// streaming STG.128 stores. Grid order: c is the FASTEST block dimension,
// so the 3 channel-blocks filling each contiguous 81KB output band region
// are co-resident -> their 1KB x 3KB-stride write chunks merge in L2 into a
// sequential DRAM drain.

namespace {
constexpr int B  = 64;
constexpr int C  = 3;
constexpr int H  = 224;
constexpr int W  = 224;      // 56 float4 per row
constexpr int N  = 27;
constexpr int G  = 9;        // pi groups of 3
constexpr int TPB = 256;

constexpr int W4      = W / 4;          // 56
constexpr int GROWS   = 32;             // rows per 3-band group (8*3 + 8)
constexpr int LOAD_V  = GROWS * W4;     // 1792 float4 per block (exactly 7*256)
constexpr int PITCH4  = 60;             // 240-float pitch (mod 32 == 16): conflict-free
constexpr int STORE_V = N * 64;         // 1728 float4 per band
constexpr int NBLOCKS = B * C * G;      // 1728

constexpr int LK = LOAD_V / TPB;        // 7, exact
constexpr int SK = 7;                   // ceil(1728/256)
}

__global__ __launch_bounds__(TPB, 7)
void overlap_patch_kernel(const float4* __restrict__ x, float4* __restrict__ out)
{
    __shared__ float4 s[GROWS * PITCH4];   // 30720 bytes

    const int bx  = blockIdx.x;
    const int c   = bx % C;                // c fastest: channel blocks adjacent
    const int g   = (bx / C) % G;
    const int b   = bx / (C * G);
    const int tid = threadIdx.x;
    const int pi0 = g * 3;

    // ---- load phase: 32 contiguous rows -> padded smem via LDGSTS ----
    const int in_base = ((b * C + c) * H + pi0 * 8) * W4;   // float4 index
    #pragma unroll
    for (int k = 0; k < LK; k++) {
        int i = tid + k * TPB;                 // 0..1791, exact (no guard)
        int row = i / W4;
        int col = i - row * W4;
        __pipeline_memcpy_async(&s[row * PITCH4 + col], &x[in_base + i], 16);
    }
    __pipeline_commit();
    __pipeline_wait_prior(0);
    __syncthreads();

    // ---- store phase: 3 bands, each fully coalesced streaming STG.128 ----
    #pragma unroll
    for (int sub = 0; sub < 3; sub++) {
        const int pi  = pi0 + sub;
        const int ob0 = ((b * (N * N) + pi * N) * C + c) * 64;
        const int srow0 = sub * 8;             // smem row offset of this band

        float4 sv[SK];
        #pragma unroll
        for (int k = 0; k < SK; k++) {
            int j = tid + k * TPB;
            if (j < STORE_V) {
                int pj = j >> 6;
                int q  = j & 63;
                int r  = q >> 2;
                int s4 = q & 3;
                sv[k] = s[(srow0 + r) * PITCH4 + pj * 2 + s4];
            }
        }
        #pragma unroll
        for (int k = 0; k < SK; k++) {
            int j = tid + k * TPB;
            if (j < STORE_V) {
                int pj = j >> 6;
                int q  = j & 63;
                __stcs(&out[ob0 + pj * (C * 64) + q], sv[k]);
            }
        }
    }
}

extern "C" void kernel_launch(void* const* d_in, const int* in_sizes, int n_in,
                              void* d_out, int out_size)
{
    const float4* x = (const float4*)d_in[0];
    float4* out = (float4*)d_out;
    overlap_patch_kernel<<<NBLOCKS, TPB>>>(x, out);
}